// round 12
// baseline (speedup 1.0000x reference)
#include <cuda_runtime.h>
#include <cuda_bf16.h>
#include <cstdint>

#define NN 50000
#define EE 600000
#define DD 128
#define KK 8
#define BB 64
#define ED 16
#define PS 8    // slices per graph for pooling

// Scratch (device globals; no runtime alloc)
__device__ float g_h[NN * DD];            // (1+eps)*x + agg
__device__ float g_xres[NN * DD];         // MLP output
__device__ float g_psum[BB * KK * DD];    // pocket sums
__device__ float g_pcnt[BB * KK];         // pocket counts
__device__ float g_pemb[BB * KK * DD];    // pocket embeddings
__device__ int   g_gstart[BB + 1];        // graph start offsets (batch sorted)
__device__ float g_part[BB * PS * KK * DD];   // pooling partials (atomic-free)
__device__ float g_cntpart[BB * PS * KK];
// Pre-converted W1/W2 in fragment-major tf32 hi/lo ([w][ktile16][ntile16][lane32][slot2])
__device__ uint32_t g_Wph[2 * 16384];
__device__ uint32_t g_Wpl[2 * 16384];

// packed-fp32 helpers (FFMA2: exact fp32 math, 2x fma-pipe throughput)
#define FMA2(acc, a2, w2) \
    asm("fma.rn.f32x2 %0, %1, %2, %0;" : "+l"(acc) : "l"(a2), "l"(w2))
#define DUP2(a2, f) \
    asm("mov.b64 %0, {%1, %1};" : "=l"(a2) : "f"(f))
#define PACK2(p, lo, hi) \
    asm("mov.b64 %0, {%1, %2};" : "=l"(p) : "f"(lo), "f"(hi))
#define UNPACK2(lo, hi, p) \
    asm("mov.b64 {%0, %1}, %2;" : "=f"(lo), "=f"(hi) : "l"(p))

// tf32 helpers
__device__ __forceinline__ uint32_t tf32_hi(float f) {
    uint32_t u;
    asm("cvt.rna.tf32.f32 %0, %1;" : "=r"(u) : "f"(f));
    return u;
}
#define MMA_TF32(d, a0, a1, a2, a3, b0, b1) \
    asm volatile("mma.sync.aligned.m16n8k8.row.col.f32.tf32.tf32.f32 " \
                 "{%0,%1,%2,%3}, {%4,%5,%6,%7}, {%8,%9}, {%0,%1,%2,%3};" \
                 : "+f"(d[0]), "+f"(d[1]), "+f"(d[2]), "+f"(d[3]) \
                 : "r"(a0), "r"(a1), "r"(a2), "r"(a3), "r"(b0), "r"(b1))

// fragment-major address of element (rr, cc) within a 16x8 (or 8x8) tile
__device__ __forceinline__ int frag_off(int rr, int cc) {
    return ((rr & 7) * 4 + (cc & 3)) * 4 + ((rr >> 3) | ((cc >> 2) << 1));
}

// ---------------------------------------------------------------------------
// Kernel 0: g_h = (1+eps)*x
// ---------------------------------------------------------------------------
__global__ void init_kernel(const float* __restrict__ x, const float* __restrict__ epsp) {
    const float c = 1.0f + epsp[0];
    int tid = blockIdx.x * blockDim.x + threadIdx.x;
    int stride = gridDim.x * blockDim.x;
    const float4* x4 = (const float4*)x;
    float4* h4 = (float4*)g_h;
    for (int i = tid; i < NN * DD / 4; i += stride) {
        float4 v = x4[i];
        v.x *= c; v.y *= c; v.z *= c; v.w *= c;
        h4[i] = v;
    }
}

// ---------------------------------------------------------------------------
// Kernel 0b: graph boundary offsets from sorted batch
// ---------------------------------------------------------------------------
__global__ void bounds_kernel(const int* __restrict__ batch) {
    int n = blockIdx.x * blockDim.x + threadIdx.x;
    if (n >= NN) return;
    int b1 = batch[n];
    int b0 = (n == 0) ? -1 : batch[n - 1];
    for (int g = b0 + 1; g <= b1; g++) g_gstart[g] = n;
    if (n == NN - 1)
        for (int g = b1 + 1; g <= BB; g++) g_gstart[g] = NN;
}

// ---------------------------------------------------------------------------
// Kernel 0c: convert W1/W2 to fragment-major tf32 hi/lo (b-frag layout of
// mma.m16n8k8: slot0 = W[k0+tr][n0+tq], slot1 = W[k0+tr+4][n0+tq])
// ---------------------------------------------------------------------------
__global__ void wconv_kernel(const float* __restrict__ W1, const float* __restrict__ W2) {
    int idx = blockIdx.x * blockDim.x + threadIdx.x;   // over 2*16*16*32
    if (idx >= 2 * 16 * 16 * 32) return;
    int w = idx >> 13;
    int rest = idx & 8191;
    int tk = rest >> 9;
    int tn = (rest >> 5) & 15;
    int lane = rest & 31;
    int tq = lane >> 2, tr = lane & 3;
    const float* W = (w == 0) ? W1 : W2;
    float v0 = W[(tk * 8 + tr) * DD + tn * 8 + tq];
    float v1 = W[(tk * 8 + tr + 4) * DD + tn * 8 + tq];
    int base = w * 16384 + (tk * 16 + tn) * 64 + lane * 2;
    uint32_t h0 = tf32_hi(v0), h1 = tf32_hi(v1);
    g_Wph[base]     = h0;
    g_Wph[base + 1] = h1;
    g_Wpl[base]     = tf32_hi(v0 - __uint_as_float(h0));
    g_Wpl[base + 1] = tf32_hi(v1 - __uint_as_float(h1));
}

// ---------------------------------------------------------------------------
// Kernel 1: edges. Warp processes 4 edges per iteration (R9 winner, unchanged)
// ---------------------------------------------------------------------------
__global__ void __launch_bounds__(256)
edge_kernel(const float* __restrict__ x,
            const int* __restrict__ ei,
            const float* __restrict__ ea,
            const float* __restrict__ We,
            const float* __restrict__ be) {
    __shared__ float sWe[ED * DD];
    __shared__ float sbe[DD];
    for (int i = threadIdx.x; i < ED * DD / 4; i += blockDim.x)
        ((float4*)sWe)[i] = ((const float4*)We)[i];
    if (threadIdx.x < DD) sbe[threadIdx.x] = be[threadIdx.x];
    __syncthreads();

    const int lane = threadIdx.x & 31;
    const int warp = blockIdx.x * (blockDim.x >> 5) + (threadIdx.x >> 5);
    const int nwarps = gridDim.x * (blockDim.x >> 5);
    const int* __restrict__ srcp = ei;
    const int* __restrict__ dstp = ei + EE;
    const int c0 = lane * 4;

    float4 bbv = *(const float4*)(&sbe[c0]);
    unsigned long long bp0, bp1;
    PACK2(bp0, bbv.x, bbv.y);
    PACK2(bp1, bbv.z, bbv.w);

    const int NG = EE / 4;
    for (int g = warp; g < NG; g += nwarps) {
        const int e0 = g * 4;
        const float* eab = ea + (size_t)e0 * ED;
        float r0 = __ldg(eab + lane);
        float r1 = __ldg(eab + lane + 32);
        int s0 = __ldg(srcp + e0 + 0), s1 = __ldg(srcp + e0 + 1);
        int s2 = __ldg(srcp + e0 + 2), s3 = __ldg(srcp + e0 + 3);
        int d0 = __ldg(dstp + e0 + 0), d1 = __ldg(dstp + e0 + 1);
        int d2 = __ldg(dstp + e0 + 2), d3 = __ldg(dstp + e0 + 3);

        unsigned long long acc[4][2];
#pragma unroll
        for (int i = 0; i < 4; i++) { acc[i][0] = bp0; acc[i][1] = bp1; }

#pragma unroll
        for (int j = 0; j < ED; j++) {
            ulonglong2 w = *(const ulonglong2*)(&sWe[j * DD + c0]);
            float a0 = __shfl_sync(0xffffffffu, r0, j);
            float a1 = __shfl_sync(0xffffffffu, r0, 16 + j);
            float a2 = __shfl_sync(0xffffffffu, r1, j);
            float a3 = __shfl_sync(0xffffffffu, r1, 16 + j);
            unsigned long long t0, t1, t2, t3;
            DUP2(t0, a0); FMA2(acc[0][0], t0, w.x); FMA2(acc[0][1], t0, w.y);
            DUP2(t1, a1); FMA2(acc[1][0], t1, w.x); FMA2(acc[1][1], t1, w.y);
            DUP2(t2, a2); FMA2(acc[2][0], t2, w.x); FMA2(acc[2][1], t2, w.y);
            DUP2(t3, a3); FMA2(acc[3][0], t3, w.x); FMA2(acc[3][1], t3, w.y);
        }

        const int sidx[4] = {s0, s1, s2, s3};
        const int didx[4] = {d0, d1, d2, d3};
#pragma unroll
        for (int i = 0; i < 4; i++) {
            float ex, ey, ez, ew;
            UNPACK2(ex, ey, acc[i][0]);
            UNPACK2(ez, ew, acc[i][1]);
            float4 xv = __ldg((const float4*)(x + (size_t)sidx[i] * DD + c0));
            float mx = fmaxf(ex + xv.x, 0.f);
            float my = fmaxf(ey + xv.y, 0.f);
            float mz = fmaxf(ez + xv.z, 0.f);
            float mw = fmaxf(ew + xv.w, 0.f);
            float* p = g_h + (size_t)didx[i] * DD + c0;
            asm volatile("red.global.add.v4.f32 [%0], {%1, %2, %3, %4};"
                         :: "l"(p), "f"(mx), "f"(my), "f"(mz), "f"(mw) : "memory");
        }
    }
}

// ---------------------------------------------------------------------------
// Kernel 2: FUSED node MLP on tensor cores, fragment-major pre-converted
// operands. Inner loop = pure LDS.128/LDS.64 + MMA (no cvt, no scalar LDS).
// sAh/sAl: A hi/lo frag-major (32KB each). sWh/sWl: W quarter stage (16KB ea).
// ---------------------------------------------------------------------------
__device__ __forceinline__ void mma_pass(const uint32_t* __restrict__ gWh,
                                         const uint32_t* __restrict__ gWl,
                                         uint32_t* __restrict__ sAh,
                                         uint32_t* __restrict__ sAl,
                                         uint32_t* __restrict__ sWh,
                                         uint32_t* __restrict__ sWl,
                                         float acc[4][2][4],
                                         int lane, int wtile2, int tid) {
#pragma unroll 1
    for (int q = 0; q < 4; q++) {
        __syncthreads();
        // stage quarter of frag-major W (4 k-tiles = 4096 u32 each for hi/lo)
        for (int i = tid; i < 1024; i += 256) {
            ((uint4*)sWh)[i] = __ldg((const uint4*)(gWh + q * 4096) + i);
            ((uint4*)sWl)[i] = __ldg((const uint4*)(gWl + q * 4096) + i);
        }
        __syncthreads();

#pragma unroll
        for (int ks = 0; ks < 4; ks++) {
            uint2 bh[2], bl[2];
#pragma unroll
            for (int ni = 0; ni < 2; ni++) {
                int wbase = (ks * 16 + wtile2 + ni) * 64 + lane * 2;
                bh[ni] = *(const uint2*)(sWh + wbase);
                bl[ni] = *(const uint2*)(sWl + wbase);
            }
            const int tkg = q * 4 + ks;
#pragma unroll
            for (int mi = 0; mi < 4; mi++) {
                const int abase = (mi * 16 + tkg) * 128 + lane * 4;
                uint4 ah = *(const uint4*)(sAh + abase);
                uint4 al = *(const uint4*)(sAl + abase);
#pragma unroll
                for (int ni = 0; ni < 2; ni++) {
                    MMA_TF32(acc[mi][ni], ah.x, ah.y, ah.z, ah.w, bh[ni].x, bh[ni].y);
                    MMA_TF32(acc[mi][ni], ah.x, ah.y, ah.z, ah.w, bl[ni].x, bl[ni].y);
                    MMA_TF32(acc[mi][ni], al.x, al.y, al.z, al.w, bh[ni].x, bh[ni].y);
                }
            }
        }
    }
}

__global__ void __launch_bounds__(256)
mlp_fused_kernel(const float* __restrict__ b1, const float* __restrict__ b2) {
    extern __shared__ uint32_t smu[];
    uint32_t* sAh = smu;              // 8192 u32 (32KB)
    uint32_t* sAl = smu + 8192;       // 8192 u32 (32KB)
    uint32_t* sWh = smu + 16384;      // 4096 u32 (16KB)
    uint32_t* sWl = smu + 20480;      // 4096 u32 (16KB)
    const int tid = threadIdx.x;
    const int row0 = blockIdx.x * 64;

    // load A tile, convert to hi/lo, store fragment-major
    for (int i = tid; i < 64 * 32; i += 256) {
        int r = i >> 5, c4 = (i & 31) * 4;
        float4 v = make_float4(0.f, 0.f, 0.f, 0.f);
        if (row0 + r < NN) v = *(const float4*)(g_h + (size_t)(row0 + r) * DD + c4);
        const float vv[4] = {v.x, v.y, v.z, v.w};
        int tm = r >> 4, rr = r & 15;
#pragma unroll
        for (int j = 0; j < 4; j++) {
            int c = c4 + j;
            int addr = (tm * 16 + (c >> 3)) * 128 + frag_off(rr, c & 7);
            uint32_t hi = tf32_hi(vv[j]);
            sAh[addr] = hi;
            sAl[addr] = tf32_hi(vv[j] - __uint_as_float(hi));
        }
    }

    const int warp = tid >> 5, lane = tid & 31;
    const int tq = lane >> 2, tr = lane & 3;
    const int wcol = warp * 16;
    const int wtile2 = warp * 2;

    float acc[4][2][4];
#pragma unroll
    for (int mi = 0; mi < 4; mi++)
#pragma unroll
        for (int ni = 0; ni < 2; ni++)
#pragma unroll
            for (int v = 0; v < 4; v++) acc[mi][ni][v] = 0.f;

    // ---- GEMM1 ----
    mma_pass(g_Wph, g_Wpl, sAh, sAl, sWh, sWl, acc, lane, wtile2, tid);
    __syncthreads();   // all warps done reading sA

    // epilogue 1: relu(acc + b1) -> sAh/sAl (fragment-major, converted)
    {
        float bias0[2], bias1[2];
#pragma unroll
        for (int ni = 0; ni < 2; ni++) {
            bias0[ni] = __ldg(b1 + wcol + ni * 8 + 2 * tr);
            bias1[ni] = __ldg(b1 + wcol + ni * 8 + 2 * tr + 1);
        }
#pragma unroll
        for (int mi = 0; mi < 4; mi++) {
#pragma unroll
            for (int ni = 0; ni < 2; ni++) {
                int tk = wtile2 + ni;
                int cc = 2 * tr;
                float v[4];
                v[0] = fmaxf(acc[mi][ni][0] + bias0[ni], 0.f);
                v[1] = fmaxf(acc[mi][ni][1] + bias1[ni], 0.f);
                v[2] = fmaxf(acc[mi][ni][2] + bias0[ni], 0.f);
                v[3] = fmaxf(acc[mi][ni][3] + bias1[ni], 0.f);
                const int rrs[4] = {tq, tq, tq + 8, tq + 8};
                const int ccs[4] = {cc, cc + 1, cc, cc + 1};
#pragma unroll
                for (int e = 0; e < 4; e++) {
                    int addr = (mi * 16 + tk) * 128 + frag_off(rrs[e], ccs[e]);
                    uint32_t hi = tf32_hi(v[e]);
                    sAh[addr] = hi;
                    sAl[addr] = tf32_hi(v[e] - __uint_as_float(hi));
                }
                acc[mi][ni][0] = 0.f; acc[mi][ni][1] = 0.f;
                acc[mi][ni][2] = 0.f; acc[mi][ni][3] = 0.f;
            }
        }
    }

    // ---- GEMM2 ---- (mma_pass starts with __syncthreads, covering epilogue writes)
    mma_pass(g_Wph + 16384, g_Wpl + 16384, sAh, sAl, sWh, sWl, acc, lane, wtile2, tid);

    // epilogue 2: acc + b2 -> g_xres
    {
        float bias0[2], bias1[2];
#pragma unroll
        for (int ni = 0; ni < 2; ni++) {
            bias0[ni] = __ldg(b2 + wcol + ni * 8 + 2 * tr);
            bias1[ni] = __ldg(b2 + wcol + ni * 8 + 2 * tr + 1);
        }
#pragma unroll
        for (int mi = 0; mi < 4; mi++) {
#pragma unroll
            for (int ni = 0; ni < 2; ni++) {
                int col = wcol + ni * 8 + 2 * tr;
                int r = row0 + mi * 16 + tq;
                if (r < NN) {
                    float2 v;
                    v.x = acc[mi][ni][0] + bias0[ni];
                    v.y = acc[mi][ni][1] + bias1[ni];
                    *(float2*)(g_xres + (size_t)r * DD + col) = v;
                }
                if (r + 8 < NN) {
                    float2 v;
                    v.x = acc[mi][ni][2] + bias0[ni];
                    v.y = acc[mi][ni][3] + bias1[ni];
                    *(float2*)(g_xres + (size_t)(r + 8) * DD + col) = v;
                }
            }
        }
    }
}

// ---------------------------------------------------------------------------
// Kernel 3: pocket pooling, atomic-free. Block = (graph b, slice s).
// ---------------------------------------------------------------------------
__global__ void pool_kernel(const float* __restrict__ mask) {
    __shared__ float sacc[8][KK * DD];
    __shared__ float scnt[8][KK];
    const int b = blockIdx.x / PS;
    const int s = blockIdx.x % PS;
    const int gs = g_gstart[b];
    const int len = g_gstart[b + 1] - gs;
    const int start = gs + (len * s) / PS;
    const int end = gs + (len * (s + 1)) / PS;

    const int wib = threadIdx.x >> 5;
    const int lane = threadIdx.x & 31;
    float* acc = sacc[wib];
    for (int i = lane; i < KK * DD; i += 32) acc[i] = 0.f;
    float cnt = 0.f;

    for (int n = start + wib; n < end; n += 8) {
        float m = (lane < KK) ? mask[(size_t)n * KK + lane] : 0.f;
        float4 xv = *(const float4*)(g_xres + (size_t)n * DD + lane * 4);
#pragma unroll
        for (int k = 0; k < KK; k++) {
            float mk = __shfl_sync(0xffffffffu, m, k);
            if (mk != 0.f) {
                float4* a = (float4*)(acc + k * DD + lane * 4);
                float4 v = *a;
                v.x += xv.x; v.y += xv.y; v.z += xv.z; v.w += xv.w;
                *a = v;
            }
        }
        cnt += m;
    }
    if (lane < KK) scnt[wib][lane] = cnt;
    __syncthreads();

    float* outp = g_part + (size_t)blockIdx.x * KK * DD;
    for (int i = threadIdx.x; i < KK * DD; i += blockDim.x) {
        float v = 0.f;
#pragma unroll
        for (int w = 0; w < 8; w++) v += sacc[w][i];
        outp[i] = v;
    }
    if (threadIdx.x < KK) {
        float c = 0.f;
#pragma unroll
        for (int w = 0; w < 8; w++) c += scnt[w][threadIdx.x];
        g_cntpart[blockIdx.x * KK + threadIdx.x] = c;
    }
}

// ---------------------------------------------------------------------------
// Kernel 3b: reduce partials -> g_psum, g_pcnt
// ---------------------------------------------------------------------------
__global__ void reduce_kernel() {
    int tid = blockIdx.x * blockDim.x + threadIdx.x;
    int stride = gridDim.x * blockDim.x;
    for (int i = tid; i < BB * KK * DD; i += stride) {
        int b = i / (KK * DD);
        int j = i % (KK * DD);
        float v = 0.f;
#pragma unroll
        for (int s = 0; s < PS; s++) v += g_part[(size_t)(b * PS + s) * KK * DD + j];
        g_psum[i] = v;
    }
    for (int i = tid; i < BB * KK; i += stride) {
        int b = i / KK;
        int k = i % KK;
        float c = 0.f;
#pragma unroll
        for (int s = 0; s < PS; s++) c += g_cntpart[(b * PS + s) * KK + k];
        g_pcnt[i] = c;
    }
}

// ---------------------------------------------------------------------------
// Kernel 4: pocket_emb = (psum/(cnt+1e-9)) @ Wv + bv. Warp per row (512 rows).
// ---------------------------------------------------------------------------
__global__ void pemb_kernel(const float* __restrict__ Wv, const float* __restrict__ bv) {
    const int lane = threadIdx.x & 31;
    const int r = blockIdx.x * (blockDim.x >> 5) + (threadIdx.x >> 5);
    if (r >= BB * KK) return;
    const float rinv = 1.f / (g_pcnt[r] + 1e-9f);
    const int c0 = lane * 4;
    float4 acc = *(const float4*)(bv + c0);
#pragma unroll 8
    for (int d = 0; d < DD; d++) {
        float a = g_psum[r * DD + d] * rinv;
        float4 w = __ldg((const float4*)(Wv + d * DD + c0));
        acc.x += a * w.x; acc.y += a * w.y; acc.z += a * w.z; acc.w += a * w.w;
    }
    *(float4*)(g_pemb + r * DD + c0) = acc;
}

// ---------------------------------------------------------------------------
// Kernel 5: residual pocket feedback + LayerNorm + ReLU. Warp per node.
// ---------------------------------------------------------------------------
__global__ void final_kernel(const float* __restrict__ mask, const int* __restrict__ batch,
                             const float* __restrict__ gamma, const float* __restrict__ beta,
                             float* __restrict__ out) {
    const int lane = threadIdx.x & 31;
    const int gw = blockIdx.x * (blockDim.x >> 5) + (threadIdx.x >> 5);
    const int tw = gridDim.x * (blockDim.x >> 5);
    const int c0 = lane * 4;
    const float4 gm = *(const float4*)(gamma + c0);
    const float4 bt = *(const float4*)(beta + c0);

    for (int n = gw; n < NN; n += tw) {
        int g = batch[n];
        float m = (lane < KK) ? mask[(size_t)n * KK + lane] : 0.f;
        float4 v = *(const float4*)(g_xres + (size_t)n * DD + c0);
        const float* pe = g_pemb + (size_t)g * KK * DD;
#pragma unroll
        for (int k = 0; k < KK; k++) {
            float mk = __shfl_sync(0xffffffffu, m, k);
            if (mk != 0.f) {
                float4 p = __ldg((const float4*)(pe + k * DD + c0));
                v.x += p.x; v.y += p.y; v.z += p.z; v.w += p.w;
            }
        }
        float s = v.x + v.y + v.z + v.w;
#pragma unroll
        for (int off = 16; off; off >>= 1) s += __shfl_xor_sync(0xffffffffu, s, off);
        float mu = s * (1.f / 128.f);
        float dx = v.x - mu, dy = v.y - mu, dz = v.z - mu, dw = v.w - mu;
        float sq = dx * dx + dy * dy + dz * dz + dw * dw;
#pragma unroll
        for (int off = 16; off; off >>= 1) sq += __shfl_xor_sync(0xffffffffu, sq, off);
        float rstd = rsqrtf(sq * (1.f / 128.f) + 1e-5f);
        float4 y;
        y.x = fmaxf(dx * rstd * gm.x + bt.x, 0.f);
        y.y = fmaxf(dy * rstd * gm.y + bt.y, 0.f);
        y.z = fmaxf(dz * rstd * gm.z + bt.z, 0.f);
        y.w = fmaxf(dw * rstd * gm.w + bt.w, 0.f);
        *(float4*)(out + (size_t)n * DD + c0) = y;
    }
}

// ---------------------------------------------------------------------------
extern "C" void kernel_launch(void* const* d_in, const int* in_sizes, int n_in,
                              void* d_out, int out_size) {
    const float* x     = (const float*)d_in[0];
    const int*   ei    = (const int*)d_in[1];
    const float* ea    = (const float*)d_in[2];
    const float* pmask = (const float*)d_in[3];
    const int*   batch = (const int*)d_in[4];
    const float* We    = (const float*)d_in[5];
    const float* be    = (const float*)d_in[6];
    const float* W1    = (const float*)d_in[7];
    const float* b1    = (const float*)d_in[8];
    const float* W2    = (const float*)d_in[9];
    const float* b2    = (const float*)d_in[10];
    const float* eps   = (const float*)d_in[11];
    const float* gamma = (const float*)d_in[12];
    const float* beta  = (const float*)d_in[13];
    const float* Wv    = (const float*)d_in[14];
    const float* bv    = (const float*)d_in[15];
    float* out = (float*)d_out;

    const int MLP_SMEM = (8192 + 8192 + 4096 + 4096) * 4;   // 98304 bytes
    cudaFuncSetAttribute(mlp_fused_kernel, cudaFuncAttributeMaxDynamicSharedMemorySize, MLP_SMEM);

    init_kernel<<<2048, 256>>>(x, eps);
    bounds_kernel<<<(NN + 255) / 256, 256>>>(batch);
    wconv_kernel<<<64, 256>>>(W1, W2);
    edge_kernel<<<4096, 256>>>(x, ei, ea, We, be);
    mlp_fused_kernel<<<(NN + 63) / 64, 256, MLP_SMEM>>>(b1, b2);
    pool_kernel<<<BB * PS, 256>>>(pmask);
    reduce_kernel<<<64, 256>>>();
    pemb_kernel<<<(BB * KK + 7) / 8, 256>>>(Wv, bv);
    final_kernel<<<2048, 256>>>(pmask, batch, gamma, beta, out);
}

// round 13
// speedup vs baseline: 1.0912x; 1.0912x over previous
#include <cuda_runtime.h>
#include <cuda_bf16.h>
#include <cstdint>

#define NN 50000
#define EE 600000
#define DD 128
#define KK 8
#define BB 64
#define ED 16
#define PS 8    // slices per graph for pooling
#define PADW 132 // padded row stride (floats) for conflict-free mma frag loads

// Scratch (device globals; no runtime alloc)
__device__ float g_h[NN * DD];            // (1+eps)*x + agg
__device__ float g_xres[NN * DD];         // MLP output
__device__ float g_psum[BB * KK * DD];    // pocket sums
__device__ float g_pcnt[BB * KK];         // pocket counts
__device__ float g_pemb[BB * KK * DD];    // pocket embeddings
__device__ int   g_gstart[BB + 1];        // graph start offsets (batch sorted)
__device__ float g_part[BB * PS * KK * DD];   // pooling partials (atomic-free)
__device__ float g_cntpart[BB * PS * KK];

// packed-fp32 helpers (FFMA2: exact fp32 math, 2x fma-pipe throughput)
#define FMA2(acc, a2, w2) \
    asm("fma.rn.f32x2 %0, %1, %2, %0;" : "+l"(acc) : "l"(a2), "l"(w2))
#define DUP2(a2, f) \
    asm("mov.b64 %0, {%1, %1};" : "=l"(a2) : "f"(f))
#define PACK2(p, lo, hi) \
    asm("mov.b64 %0, {%1, %2};" : "=l"(p) : "f"(lo), "f"(hi))
#define UNPACK2(lo, hi, p) \
    asm("mov.b64 {%0, %1}, %2;" : "=f"(lo), "=f"(hi) : "l"(p))

// tf32 helpers
__device__ __forceinline__ uint32_t tf32_hi(float f) {
    uint32_t u;
    asm("cvt.rna.tf32.f32 %0, %1;" : "=r"(u) : "f"(f));
    return u;
}
#define MMA_TF32(d, a0, a1, a2, a3, b0, b1) \
    asm volatile("mma.sync.aligned.m16n8k8.row.col.f32.tf32.tf32.f32 " \
                 "{%0,%1,%2,%3}, {%4,%5,%6,%7}, {%8,%9}, {%0,%1,%2,%3};" \
                 : "+f"(d[0]), "+f"(d[1]), "+f"(d[2]), "+f"(d[3]) \
                 : "r"(a0), "r"(a1), "r"(a2), "r"(a3), "r"(b0), "r"(b1))

// ---------------------------------------------------------------------------
// Kernel 0: g_h = (1+eps)*x
// ---------------------------------------------------------------------------
__global__ void init_kernel(const float* __restrict__ x, const float* __restrict__ epsp) {
    const float c = 1.0f + epsp[0];
    int tid = blockIdx.x * blockDim.x + threadIdx.x;
    int stride = gridDim.x * blockDim.x;
    const float4* x4 = (const float4*)x;
    float4* h4 = (float4*)g_h;
    for (int i = tid; i < NN * DD / 4; i += stride) {
        float4 v = x4[i];
        v.x *= c; v.y *= c; v.z *= c; v.w *= c;
        h4[i] = v;
    }
}

// ---------------------------------------------------------------------------
// Kernel 0b: graph boundary offsets from sorted batch
// ---------------------------------------------------------------------------
__global__ void bounds_kernel(const int* __restrict__ batch) {
    int n = blockIdx.x * blockDim.x + threadIdx.x;
    if (n >= NN) return;
    int b1 = batch[n];
    int b0 = (n == 0) ? -1 : batch[n - 1];
    for (int g = b0 + 1; g <= b1; g++) g_gstart[g] = n;
    if (n == NN - 1)
        for (int g = b1 + 1; g <= BB; g++) g_gstart[g] = NN;
}

// ---------------------------------------------------------------------------
// Kernel 1: edges. Warp processes 8 edges per iteration: sWe row loaded ONCE
// per j per 8 edges (halves L1 wavefronts/edge vs 4-edge version; L1 was
// 87.8% and is the binding pipe). Index loads deferred to epilogue to keep
// j-loop register pressure low (no spill).
// ---------------------------------------------------------------------------
__global__ void __launch_bounds__(256)
edge_kernel(const float* __restrict__ x,
            const int* __restrict__ ei,
            const float* __restrict__ ea,
            const float* __restrict__ We,
            const float* __restrict__ be) {
    __shared__ float sWe[ED * DD];
    __shared__ float sbe[DD];
    for (int i = threadIdx.x; i < ED * DD / 4; i += blockDim.x)
        ((float4*)sWe)[i] = ((const float4*)We)[i];
    if (threadIdx.x < DD) sbe[threadIdx.x] = be[threadIdx.x];
    __syncthreads();

    const int lane = threadIdx.x & 31;
    const int warp = blockIdx.x * (blockDim.x >> 5) + (threadIdx.x >> 5);
    const int nwarps = gridDim.x * (blockDim.x >> 5);
    const int* __restrict__ srcp = ei;
    const int* __restrict__ dstp = ei + EE;
    const int c0 = lane * 4;

    float4 bbv = *(const float4*)(&sbe[c0]);
    unsigned long long bp0, bp1;
    PACK2(bp0, bbv.x, bbv.y);
    PACK2(bp1, bbv.z, bbv.w);

    const int NG = EE / 8;   // 75000 groups of 8 edges
    for (int g = warp; g < NG; g += nwarps) {
        const int e0 = g * 8;
        // stage 8 edges' attrs: 128 floats, 4 per lane, coalesced
        const float* eab = ea + (size_t)e0 * ED;
        float r[4];
        r[0] = __ldg(eab + lane);
        r[1] = __ldg(eab + lane + 32);
        r[2] = __ldg(eab + lane + 64);
        r[3] = __ldg(eab + lane + 96);

        unsigned long long acc[8][2];
#pragma unroll
        for (int i = 0; i < 8; i++) { acc[i][0] = bp0; acc[i][1] = bp1; }

#pragma unroll
        for (int j = 0; j < ED; j++) {
            ulonglong2 w = *(const ulonglong2*)(&sWe[j * DD + c0]);
#pragma unroll
            for (int i = 0; i < 8; i++) {
                // edge i, attr j lives at flat index i*16+j -> r[i>>1], lane (i&1)*16+j
                float a = __shfl_sync(0xffffffffu, r[i >> 1], ((i & 1) << 4) + j);
                unsigned long long t;
                DUP2(t, a);
                FMA2(acc[i][0], t, w.x);
                FMA2(acc[i][1], t, w.y);
            }
        }

#pragma unroll
        for (int i = 0; i < 8; i++) {
            int s = __ldg(srcp + e0 + i);
            int d = __ldg(dstp + e0 + i);
            float ex, ey, ez, ew;
            UNPACK2(ex, ey, acc[i][0]);
            UNPACK2(ez, ew, acc[i][1]);
            float4 xv = __ldg((const float4*)(x + (size_t)s * DD + c0));
            float mx = fmaxf(ex + xv.x, 0.f);
            float my = fmaxf(ey + xv.y, 0.f);
            float mz = fmaxf(ez + xv.z, 0.f);
            float mw = fmaxf(ew + xv.w, 0.f);
            float* p = g_h + (size_t)d * DD + c0;
            asm volatile("red.global.add.v4.f32 [%0], {%1, %2, %3, %4};"
                         :: "l"(p), "f"(mx), "f"(my), "f"(mz), "f"(mw) : "memory");
        }
    }
}

// ---------------------------------------------------------------------------
// Kernel 2: FUSED node MLP on tensor cores (R11 winner, unchanged).
// mma.sync m16n8k8 tf32, 3xTF32 split; 64-row tile; 50KB smem, 4 blocks/SM.
// ---------------------------------------------------------------------------
__device__ __forceinline__ void mma_gemm_pass(const float* __restrict__ W,
                                              float* __restrict__ sW,
                                              const float* __restrict__ sA,
                                              float acc[4][2][4],
                                              int tq, int tr, int wcol, int tid) {
#pragma unroll 1
    for (int q = 0; q < 4; q++) {
        __syncthreads();
        for (int i = tid; i < 32 * 32; i += 256) {
            int r = i >> 5, c4 = i & 31;
            *(float4*)(sW + r * PADW + c4 * 4) =
                ((const float4*)(W + (size_t)(q * 32 + r) * DD))[c4];
        }
        __syncthreads();

#pragma unroll
        for (int ks = 0; ks < 4; ks++) {
            const int k0 = ks * 8;
            uint32_t bh[2][2], bl[2][2];
#pragma unroll
            for (int ni = 0; ni < 2; ni++) {
                int col = wcol + ni * 8 + tq;
                float w0 = sW[(k0 + tr) * PADW + col];
                float w1 = sW[(k0 + tr + 4) * PADW + col];
                bh[ni][0] = tf32_hi(w0);
                bl[ni][0] = tf32_hi(w0 - __uint_as_float(bh[ni][0]));
                bh[ni][1] = tf32_hi(w1);
                bl[ni][1] = tf32_hi(w1 - __uint_as_float(bh[ni][1]));
            }
            const int kg = q * 32 + k0;
#pragma unroll
            for (int mi = 0; mi < 4; mi++) {
                const float* ap = sA + (mi * 16 + tq) * PADW + kg + tr;
                float a0 = ap[0];
                float a1 = ap[8 * PADW];
                float a2 = ap[4];
                float a3 = ap[8 * PADW + 4];
                uint32_t ah0 = tf32_hi(a0), ah1 = tf32_hi(a1);
                uint32_t ah2 = tf32_hi(a2), ah3 = tf32_hi(a3);
                uint32_t al0 = tf32_hi(a0 - __uint_as_float(ah0));
                uint32_t al1 = tf32_hi(a1 - __uint_as_float(ah1));
                uint32_t al2 = tf32_hi(a2 - __uint_as_float(ah2));
                uint32_t al3 = tf32_hi(a3 - __uint_as_float(ah3));
#pragma unroll
                for (int ni = 0; ni < 2; ni++) {
                    MMA_TF32(acc[mi][ni], ah0, ah1, ah2, ah3, bh[ni][0], bh[ni][1]);
                    MMA_TF32(acc[mi][ni], ah0, ah1, ah2, ah3, bl[ni][0], bl[ni][1]);
                    MMA_TF32(acc[mi][ni], al0, al1, al2, al3, bh[ni][0], bh[ni][1]);
                }
            }
        }
    }
}

__global__ void __launch_bounds__(256, 4)
mlp_fused_kernel(const float* __restrict__ W1, const float* __restrict__ b1,
                 const float* __restrict__ W2, const float* __restrict__ b2) {
    extern __shared__ float sm[];
    float* sW = sm;                  // 32 x PADW
    float* sA = sm + 32 * PADW;      // 64 x PADW
    const int tid = threadIdx.x;
    const int row0 = blockIdx.x * 64;

    for (int i = tid; i < 64 * 32; i += 256) {
        int r = i >> 5, c4 = i & 31;
        float4 v = make_float4(0.f, 0.f, 0.f, 0.f);
        if (row0 + r < NN) v = ((const float4*)(g_h + (size_t)(row0 + r) * DD))[c4];
        *(float4*)(sA + r * PADW + c4 * 4) = v;
    }

    const int warp = tid >> 5, lane = tid & 31;
    const int tq = lane >> 2;
    const int tr = lane & 3;
    const int wcol = warp * 16;

    float acc[4][2][4];
#pragma unroll
    for (int mi = 0; mi < 4; mi++)
#pragma unroll
        for (int ni = 0; ni < 2; ni++)
#pragma unroll
            for (int v = 0; v < 4; v++) acc[mi][ni][v] = 0.f;

    // ---- GEMM1 ----
    mma_gemm_pass(W1, sW, sA, acc, tq, tr, wcol, tid);
    __syncthreads();

    // epilogue 1: relu(acc + b1) -> sA
    {
        float bias[2][2];
#pragma unroll
        for (int ni = 0; ni < 2; ni++) {
            bias[ni][0] = __ldg(b1 + wcol + ni * 8 + 2 * tr);
            bias[ni][1] = __ldg(b1 + wcol + ni * 8 + 2 * tr + 1);
        }
#pragma unroll
        for (int mi = 0; mi < 4; mi++) {
#pragma unroll
            for (int ni = 0; ni < 2; ni++) {
                int col = wcol + ni * 8 + 2 * tr;
                int r = mi * 16 + tq;
                float2 v0;
                v0.x = fmaxf(acc[mi][ni][0] + bias[ni][0], 0.f);
                v0.y = fmaxf(acc[mi][ni][1] + bias[ni][1], 0.f);
                *(float2*)(sA + r * PADW + col) = v0;
                float2 v1;
                v1.x = fmaxf(acc[mi][ni][2] + bias[ni][0], 0.f);
                v1.y = fmaxf(acc[mi][ni][3] + bias[ni][1], 0.f);
                *(float2*)(sA + (r + 8) * PADW + col) = v1;
                acc[mi][ni][0] = 0.f; acc[mi][ni][1] = 0.f;
                acc[mi][ni][2] = 0.f; acc[mi][ni][3] = 0.f;
            }
        }
    }
    __syncthreads();

    // ---- GEMM2 ----
    mma_gemm_pass(W2, sW, sA, acc, tq, tr, wcol, tid);

    // epilogue 2: acc + b2 -> g_xres
    {
        float bias[2][2];
#pragma unroll
        for (int ni = 0; ni < 2; ni++) {
            bias[ni][0] = __ldg(b2 + wcol + ni * 8 + 2 * tr);
            bias[ni][1] = __ldg(b2 + wcol + ni * 8 + 2 * tr + 1);
        }
#pragma unroll
        for (int mi = 0; mi < 4; mi++) {
#pragma unroll
            for (int ni = 0; ni < 2; ni++) {
                int col = wcol + ni * 8 + 2 * tr;
                int r = row0 + mi * 16 + tq;
                if (r < NN) {
                    float2 v;
                    v.x = acc[mi][ni][0] + bias[ni][0];
                    v.y = acc[mi][ni][1] + bias[ni][1];
                    *(float2*)(g_xres + (size_t)r * DD + col) = v;
                }
                if (r + 8 < NN) {
                    float2 v;
                    v.x = acc[mi][ni][2] + bias[ni][0];
                    v.y = acc[mi][ni][3] + bias[ni][1];
                    *(float2*)(g_xres + (size_t)(r + 8) * DD + col) = v;
                }
            }
        }
    }
}

// ---------------------------------------------------------------------------
// Kernel 3: pocket pooling, atomic-free. Block = (graph b, slice s).
// ---------------------------------------------------------------------------
__global__ void pool_kernel(const float* __restrict__ mask) {
    __shared__ float sacc[8][KK * DD];
    __shared__ float scnt[8][KK];
    const int b = blockIdx.x / PS;
    const int s = blockIdx.x % PS;
    const int gs = g_gstart[b];
    const int len = g_gstart[b + 1] - gs;
    const int start = gs + (len * s) / PS;
    const int end = gs + (len * (s + 1)) / PS;

    const int wib = threadIdx.x >> 5;
    const int lane = threadIdx.x & 31;
    float* acc = sacc[wib];
    for (int i = lane; i < KK * DD; i += 32) acc[i] = 0.f;
    float cnt = 0.f;

    for (int n = start + wib; n < end; n += 8) {
        float m = (lane < KK) ? mask[(size_t)n * KK + lane] : 0.f;
        float4 xv = *(const float4*)(g_xres + (size_t)n * DD + lane * 4);
#pragma unroll
        for (int k = 0; k < KK; k++) {
            float mk = __shfl_sync(0xffffffffu, m, k);
            if (mk != 0.f) {
                float4* a = (float4*)(acc + k * DD + lane * 4);
                float4 v = *a;
                v.x += xv.x; v.y += xv.y; v.z += xv.z; v.w += xv.w;
                *a = v;
            }
        }
        cnt += m;
    }
    if (lane < KK) scnt[wib][lane] = cnt;
    __syncthreads();

    float* outp = g_part + (size_t)blockIdx.x * KK * DD;
    for (int i = threadIdx.x; i < KK * DD; i += blockDim.x) {
        float v = 0.f;
#pragma unroll
        for (int w = 0; w < 8; w++) v += sacc[w][i];
        outp[i] = v;
    }
    if (threadIdx.x < KK) {
        float c = 0.f;
#pragma unroll
        for (int w = 0; w < 8; w++) c += scnt[w][threadIdx.x];
        g_cntpart[blockIdx.x * KK + threadIdx.x] = c;
    }
}

// ---------------------------------------------------------------------------
// Kernel 3b: reduce partials -> g_psum, g_pcnt
// ---------------------------------------------------------------------------
__global__ void reduce_kernel() {
    int tid = blockIdx.x * blockDim.x + threadIdx.x;
    int stride = gridDim.x * blockDim.x;
    for (int i = tid; i < BB * KK * DD; i += stride) {
        int b = i / (KK * DD);
        int j = i % (KK * DD);
        float v = 0.f;
#pragma unroll
        for (int s = 0; s < PS; s++) v += g_part[(size_t)(b * PS + s) * KK * DD + j];
        g_psum[i] = v;
    }
    for (int i = tid; i < BB * KK; i += stride) {
        int b = i / KK;
        int k = i % KK;
        float c = 0.f;
#pragma unroll
        for (int s = 0; s < PS; s++) c += g_cntpart[(b * PS + s) * KK + k];
        g_pcnt[i] = c;
    }
}

// ---------------------------------------------------------------------------
// Kernel 4: pocket_emb = (psum/(cnt+1e-9)) @ Wv + bv. Warp per row (512 rows).
// ---------------------------------------------------------------------------
__global__ void pemb_kernel(const float* __restrict__ Wv, const float* __restrict__ bv) {
    const int lane = threadIdx.x & 31;
    const int r = blockIdx.x * (blockDim.x >> 5) + (threadIdx.x >> 5);
    if (r >= BB * KK) return;
    const float rinv = 1.f / (g_pcnt[r] + 1e-9f);
    const int c0 = lane * 4;
    float4 acc = *(const float4*)(bv + c0);
#pragma unroll 8
    for (int d = 0; d < DD; d++) {
        float a = g_psum[r * DD + d] * rinv;
        float4 w = __ldg((const float4*)(Wv + d * DD + c0));
        acc.x += a * w.x; acc.y += a * w.y; acc.z += a * w.z; acc.w += a * w.w;
    }
    *(float4*)(g_pemb + r * DD + c0) = acc;
}

// ---------------------------------------------------------------------------
// Kernel 5: residual pocket feedback + LayerNorm + ReLU. Warp per node.
// ---------------------------------------------------------------------------
__global__ void final_kernel(const float* __restrict__ mask, const int* __restrict__ batch,
                             const float* __restrict__ gamma, const float* __restrict__ beta,
                             float* __restrict__ out) {
    const int lane = threadIdx.x & 31;
    const int gw = blockIdx.x * (blockDim.x >> 5) + (threadIdx.x >> 5);
    const int tw = gridDim.x * (blockDim.x >> 5);
    const int c0 = lane * 4;
    const float4 gm = *(const float4*)(gamma + c0);
    const float4 bt = *(const float4*)(beta + c0);

    for (int n = gw; n < NN; n += tw) {
        int g = batch[n];
        float m = (lane < KK) ? mask[(size_t)n * KK + lane] : 0.f;
        float4 v = *(const float4*)(g_xres + (size_t)n * DD + c0);
        const float* pe = g_pemb + (size_t)g * KK * DD;
#pragma unroll
        for (int k = 0; k < KK; k++) {
            float mk = __shfl_sync(0xffffffffu, m, k);
            if (mk != 0.f) {
                float4 p = __ldg((const float4*)(pe + k * DD + c0));
                v.x += p.x; v.y += p.y; v.z += p.z; v.w += p.w;
            }
        }
        float s = v.x + v.y + v.z + v.w;
#pragma unroll
        for (int off = 16; off; off >>= 1) s += __shfl_xor_sync(0xffffffffu, s, off);
        float mu = s * (1.f / 128.f);
        float dx = v.x - mu, dy = v.y - mu, dz = v.z - mu, dw = v.w - mu;
        float sq = dx * dx + dy * dy + dz * dz + dw * dw;
#pragma unroll
        for (int off = 16; off; off >>= 1) sq += __shfl_xor_sync(0xffffffffu, sq, off);
        float rstd = rsqrtf(sq * (1.f / 128.f) + 1e-5f);
        float4 y;
        y.x = fmaxf(dx * rstd * gm.x + bt.x, 0.f);
        y.y = fmaxf(dy * rstd * gm.y + bt.y, 0.f);
        y.z = fmaxf(dz * rstd * gm.z + bt.z, 0.f);
        y.w = fmaxf(dw * rstd * gm.w + bt.w, 0.f);
        *(float4*)(out + (size_t)n * DD + c0) = y;
    }
}

// ---------------------------------------------------------------------------
extern "C" void kernel_launch(void* const* d_in, const int* in_sizes, int n_in,
                              void* d_out, int out_size) {
    const float* x     = (const float*)d_in[0];
    const int*   ei    = (const int*)d_in[1];
    const float* ea    = (const float*)d_in[2];
    const float* pmask = (const float*)d_in[3];
    const int*   batch = (const int*)d_in[4];
    const float* We    = (const float*)d_in[5];
    const float* be    = (const float*)d_in[6];
    const float* W1    = (const float*)d_in[7];
    const float* b1    = (const float*)d_in[8];
    const float* W2    = (const float*)d_in[9];
    const float* b2    = (const float*)d_in[10];
    const float* eps   = (const float*)d_in[11];
    const float* gamma = (const float*)d_in[12];
    const float* beta  = (const float*)d_in[13];
    const float* Wv    = (const float*)d_in[14];
    const float* bv    = (const float*)d_in[15];
    float* out = (float*)d_out;

    const int MLP_SMEM = (32 + 64) * PADW * 4;   // 50688 bytes
    cudaFuncSetAttribute(mlp_fused_kernel, cudaFuncAttributeMaxDynamicSharedMemorySize, MLP_SMEM);

    init_kernel<<<2048, 256>>>(x, eps);
    bounds_kernel<<<(NN + 255) / 256, 256>>>(batch);
    edge_kernel<<<4096, 256>>>(x, ei, ea, We, be);
    mlp_fused_kernel<<<(NN + 63) / 64, 256, MLP_SMEM>>>(W1, b1, W2, b2);
    pool_kernel<<<BB * PS, 256>>>(pmask);
    reduce_kernel<<<64, 256>>>();
    pemb_kernel<<<(BB * KK + 7) / 8, 256>>>(Wv, bv);
    final_kernel<<<2048, 256>>>(pmask, batch, gamma, beta, out);
}

// round 14
// speedup vs baseline: 1.0940x; 1.0025x over previous
#include <cuda_runtime.h>
#include <cuda_bf16.h>
#include <cstdint>

#define NN 50000
#define EE 600000
#define DD 128
#define KK 8
#define BB 64
#define ED 16
#define PS 8    // slices per graph for pooling
#define PADW 132 // padded row stride (floats) for conflict-free mma frag loads

// Scratch (device globals; no runtime alloc)
__device__ float g_h[NN * DD];            // (1+eps)*x + agg
__device__ float g_xres[NN * DD];         // MLP output
__device__ float g_psum[BB * KK * DD];    // pocket sums
__device__ float g_pcnt[BB * KK];         // pocket counts
__device__ float g_pemb[BB * KK * DD];    // pocket embeddings
__device__ int   g_gstart[BB + 1];        // graph start offsets (batch sorted)
__device__ float g_part[BB * PS * KK * DD];   // pooling partials (atomic-free)
__device__ float g_cntpart[BB * PS * KK];
// Pre-converted W1/W2, fragment-major tf32 hi/lo ([w][ktile16][ntile16][lane32][slot2])
__device__ uint32_t g_Wph[2 * 16384];
__device__ uint32_t g_Wpl[2 * 16384];

// packed-fp32 helpers (FFMA2: exact fp32 math, 2x fma-pipe throughput)
#define FMA2(acc, a2, w2) \
    asm("fma.rn.f32x2 %0, %1, %2, %0;" : "+l"(acc) : "l"(a2), "l"(w2))
#define DUP2(a2, f) \
    asm("mov.b64 %0, {%1, %1};" : "=l"(a2) : "f"(f))
#define PACK2(p, lo, hi) \
    asm("mov.b64 %0, {%1, %2};" : "=l"(p) : "f"(lo), "f"(hi))
#define UNPACK2(lo, hi, p) \
    asm("mov.b64 {%0, %1}, %2;" : "=f"(lo), "=f"(hi) : "l"(p))

// tf32 helpers
__device__ __forceinline__ uint32_t tf32_hi(float f) {
    uint32_t u;
    asm("cvt.rna.tf32.f32 %0, %1;" : "=r"(u) : "f"(f));
    return u;
}
#define MMA_TF32(d, a0, a1, a2, a3, b0, b1) \
    asm volatile("mma.sync.aligned.m16n8k8.row.col.f32.tf32.tf32.f32 " \
                 "{%0,%1,%2,%3}, {%4,%5,%6,%7}, {%8,%9}, {%0,%1,%2,%3};" \
                 : "+f"(d[0]), "+f"(d[1]), "+f"(d[2]), "+f"(d[3]) \
                 : "r"(a0), "r"(a1), "r"(a2), "r"(a3), "r"(b0), "r"(b1))

// ---------------------------------------------------------------------------
// Kernel 0: g_h = (1+eps)*x
// ---------------------------------------------------------------------------
__global__ void init_kernel(const float* __restrict__ x, const float* __restrict__ epsp) {
    const float c = 1.0f + epsp[0];
    int tid = blockIdx.x * blockDim.x + threadIdx.x;
    int stride = gridDim.x * blockDim.x;
    const float4* x4 = (const float4*)x;
    float4* h4 = (float4*)g_h;
    for (int i = tid; i < NN * DD / 4; i += stride) {
        float4 v = x4[i];
        v.x *= c; v.y *= c; v.z *= c; v.w *= c;
        h4[i] = v;
    }
}

// ---------------------------------------------------------------------------
// Kernel 0b: graph boundary offsets from sorted batch
// ---------------------------------------------------------------------------
__global__ void bounds_kernel(const int* __restrict__ batch) {
    int n = blockIdx.x * blockDim.x + threadIdx.x;
    if (n >= NN) return;
    int b1 = batch[n];
    int b0 = (n == 0) ? -1 : batch[n - 1];
    for (int g = b0 + 1; g <= b1; g++) g_gstart[g] = n;
    if (n == NN - 1)
        for (int g = b1 + 1; g <= BB; g++) g_gstart[g] = NN;
}

// ---------------------------------------------------------------------------
// Kernel 0c: convert W1/W2 to fragment-major tf32 hi/lo (b-frag layout of
// mma.m16n8k8: slot0 = W[k0+tr][n0+tq], slot1 = W[k0+tr+4][n0+tq]).
// Layout verified in R12 (passed with rel_err 7.2e-7).
// ---------------------------------------------------------------------------
__global__ void wconv_kernel(const float* __restrict__ W1, const float* __restrict__ W2) {
    int idx = blockIdx.x * blockDim.x + threadIdx.x;   // over 2*16*16*32
    if (idx >= 2 * 16 * 16 * 32) return;
    int w = idx >> 13;
    int rest = idx & 8191;
    int tk = rest >> 9;
    int tn = (rest >> 5) & 15;
    int lane = rest & 31;
    int tq = lane >> 2, tr = lane & 3;
    const float* W = (w == 0) ? W1 : W2;
    float v0 = W[(tk * 8 + tr) * DD + tn * 8 + tq];
    float v1 = W[(tk * 8 + tr + 4) * DD + tn * 8 + tq];
    int base = w * 16384 + (tk * 16 + tn) * 64 + lane * 2;
    uint32_t h0 = tf32_hi(v0), h1 = tf32_hi(v1);
    g_Wph[base]     = h0;
    g_Wph[base + 1] = h1;
    g_Wpl[base]     = tf32_hi(v0 - __uint_as_float(h0));
    g_Wpl[base + 1] = tf32_hi(v1 - __uint_as_float(h1));
}

// ---------------------------------------------------------------------------
// Kernel 1: edges. Warp processes 8 edges per iteration (R13 winner, unchanged)
// ---------------------------------------------------------------------------
__global__ void __launch_bounds__(256)
edge_kernel(const float* __restrict__ x,
            const int* __restrict__ ei,
            const float* __restrict__ ea,
            const float* __restrict__ We,
            const float* __restrict__ be) {
    __shared__ float sWe[ED * DD];
    __shared__ float sbe[DD];
    for (int i = threadIdx.x; i < ED * DD / 4; i += blockDim.x)
        ((float4*)sWe)[i] = ((const float4*)We)[i];
    if (threadIdx.x < DD) sbe[threadIdx.x] = be[threadIdx.x];
    __syncthreads();

    const int lane = threadIdx.x & 31;
    const int warp = blockIdx.x * (blockDim.x >> 5) + (threadIdx.x >> 5);
    const int nwarps = gridDim.x * (blockDim.x >> 5);
    const int* __restrict__ srcp = ei;
    const int* __restrict__ dstp = ei + EE;
    const int c0 = lane * 4;

    float4 bbv = *(const float4*)(&sbe[c0]);
    unsigned long long bp0, bp1;
    PACK2(bp0, bbv.x, bbv.y);
    PACK2(bp1, bbv.z, bbv.w);

    const int NG = EE / 8;   // 75000 groups of 8 edges
    for (int g = warp; g < NG; g += nwarps) {
        const int e0 = g * 8;
        const float* eab = ea + (size_t)e0 * ED;
        float r[4];
        r[0] = __ldg(eab + lane);
        r[1] = __ldg(eab + lane + 32);
        r[2] = __ldg(eab + lane + 64);
        r[3] = __ldg(eab + lane + 96);

        unsigned long long acc[8][2];
#pragma unroll
        for (int i = 0; i < 8; i++) { acc[i][0] = bp0; acc[i][1] = bp1; }

#pragma unroll
        for (int j = 0; j < ED; j++) {
            ulonglong2 w = *(const ulonglong2*)(&sWe[j * DD + c0]);
#pragma unroll
            for (int i = 0; i < 8; i++) {
                float a = __shfl_sync(0xffffffffu, r[i >> 1], ((i & 1) << 4) + j);
                unsigned long long t;
                DUP2(t, a);
                FMA2(acc[i][0], t, w.x);
                FMA2(acc[i][1], t, w.y);
            }
        }

#pragma unroll
        for (int i = 0; i < 8; i++) {
            int s = __ldg(srcp + e0 + i);
            int d = __ldg(dstp + e0 + i);
            float ex, ey, ez, ew;
            UNPACK2(ex, ey, acc[i][0]);
            UNPACK2(ez, ew, acc[i][1]);
            float4 xv = __ldg((const float4*)(x + (size_t)s * DD + c0));
            float mx = fmaxf(ex + xv.x, 0.f);
            float my = fmaxf(ey + xv.y, 0.f);
            float mz = fmaxf(ez + xv.z, 0.f);
            float mw = fmaxf(ew + xv.w, 0.f);
            float* p = g_h + (size_t)d * DD + c0;
            asm volatile("red.global.add.v4.f32 [%0], {%1, %2, %3, %4};"
                         :: "l"(p), "f"(mx), "f"(my), "f"(mz), "f"(mw) : "memory");
        }
    }
}

// ---------------------------------------------------------------------------
// Kernel 2: FUSED node MLP on tensor cores. Same tiling/occupancy as R13
// winner (64-row tile, 4 blocks/SM, sA fp32 padded), but:
//  - B frags loaded pre-converted (LDG.64 from g_Wph/g_Wpl, L2-hot):
//    removes sW smem stage + 16 barriers + all B-side cvt.
//  - A lo-term fed as raw fp32 bits (tf32 datapath truncates low mantissa):
//    halves A-side cvt count. Error added ~2^-22, negligible.
// ---------------------------------------------------------------------------
__device__ __forceinline__ void mma_gemm_pass(const uint32_t* __restrict__ gWh,
                                              const uint32_t* __restrict__ gWl,
                                              const float* __restrict__ sA,
                                              float acc[4][2][4],
                                              int tq, int tr, int wtile2, int lane) {
#pragma unroll 1
    for (int tk = 0; tk < 16; tk++) {
        uint2 bh[2], bl[2];
#pragma unroll
        for (int ni = 0; ni < 2; ni++) {
            int wbase = (tk * 16 + wtile2 + ni) * 64 + lane * 2;
            bh[ni] = __ldg((const uint2*)(gWh + wbase));
            bl[ni] = __ldg((const uint2*)(gWl + wbase));
        }
        const int kg = tk * 8;
#pragma unroll
        for (int mi = 0; mi < 4; mi++) {
            const float* ap = sA + (mi * 16 + tq) * PADW + kg + tr;
            float a0 = ap[0];
            float a1 = ap[8 * PADW];
            float a2 = ap[4];
            float a3 = ap[8 * PADW + 4];
            uint32_t ah0 = tf32_hi(a0), ah1 = tf32_hi(a1);
            uint32_t ah2 = tf32_hi(a2), ah3 = tf32_hi(a3);
            // lo terms: raw fp32 bits (HW truncates to tf32; err ~2^-22 of a)
            uint32_t al0 = __float_as_uint(a0 - __uint_as_float(ah0));
            uint32_t al1 = __float_as_uint(a1 - __uint_as_float(ah1));
            uint32_t al2 = __float_as_uint(a2 - __uint_as_float(ah2));
            uint32_t al3 = __float_as_uint(a3 - __uint_as_float(ah3));
#pragma unroll
            for (int ni = 0; ni < 2; ni++) {
                MMA_TF32(acc[mi][ni], ah0, ah1, ah2, ah3, bh[ni].x, bh[ni].y);
                MMA_TF32(acc[mi][ni], ah0, ah1, ah2, ah3, bl[ni].x, bl[ni].y);
                MMA_TF32(acc[mi][ni], al0, al1, al2, al3, bh[ni].x, bh[ni].y);
            }
        }
    }
}

__global__ void __launch_bounds__(256, 4)
mlp_fused_kernel(const float* __restrict__ b1, const float* __restrict__ b2) {
    extern __shared__ float sm[];
    float* sA = sm;                  // 64 x PADW (33.8KB)
    const int tid = threadIdx.x;
    const int row0 = blockIdx.x * 64;

    for (int i = tid; i < 64 * 32; i += 256) {
        int r = i >> 5, c4 = i & 31;
        float4 v = make_float4(0.f, 0.f, 0.f, 0.f);
        if (row0 + r < NN) v = ((const float4*)(g_h + (size_t)(row0 + r) * DD))[c4];
        *(float4*)(sA + r * PADW + c4 * 4) = v;
    }
    __syncthreads();

    const int warp = tid >> 5, lane = tid & 31;
    const int tq = lane >> 2;
    const int tr = lane & 3;
    const int wcol = warp * 16;
    const int wtile2 = warp * 2;

    float acc[4][2][4];
#pragma unroll
    for (int mi = 0; mi < 4; mi++)
#pragma unroll
        for (int ni = 0; ni < 2; ni++)
#pragma unroll
            for (int v = 0; v < 4; v++) acc[mi][ni][v] = 0.f;

    // ---- GEMM1 ----
    mma_gemm_pass(g_Wph, g_Wpl, sA, acc, tq, tr, wtile2, lane);
    __syncthreads();   // all warps done reading sA before epilogue overwrites it

    // epilogue 1: relu(acc + b1) -> sA
    {
        float bias[2][2];
#pragma unroll
        for (int ni = 0; ni < 2; ni++) {
            bias[ni][0] = __ldg(b1 + wcol + ni * 8 + 2 * tr);
            bias[ni][1] = __ldg(b1 + wcol + ni * 8 + 2 * tr + 1);
        }
#pragma unroll
        for (int mi = 0; mi < 4; mi++) {
#pragma unroll
            for (int ni = 0; ni < 2; ni++) {
                int col = wcol + ni * 8 + 2 * tr;
                int r = mi * 16 + tq;
                float2 v0;
                v0.x = fmaxf(acc[mi][ni][0] + bias[ni][0], 0.f);
                v0.y = fmaxf(acc[mi][ni][1] + bias[ni][1], 0.f);
                *(float2*)(sA + r * PADW + col) = v0;
                float2 v1;
                v1.x = fmaxf(acc[mi][ni][2] + bias[ni][0], 0.f);
                v1.y = fmaxf(acc[mi][ni][3] + bias[ni][1], 0.f);
                *(float2*)(sA + (r + 8) * PADW + col) = v1;
                acc[mi][ni][0] = 0.f; acc[mi][ni][1] = 0.f;
                acc[mi][ni][2] = 0.f; acc[mi][ni][3] = 0.f;
            }
        }
    }
    __syncthreads();   // epilogue writes visible before GEMM2 reads sA

    // ---- GEMM2 ----
    mma_gemm_pass(g_Wph + 16384, g_Wpl + 16384, sA, acc, tq, tr, wtile2, lane);

    // epilogue 2: acc + b2 -> g_xres
    {
        float bias[2][2];
#pragma unroll
        for (int ni = 0; ni < 2; ni++) {
            bias[ni][0] = __ldg(b2 + wcol + ni * 8 + 2 * tr);
            bias[ni][1] = __ldg(b2 + wcol + ni * 8 + 2 * tr + 1);
        }
#pragma unroll
        for (int mi = 0; mi < 4; mi++) {
#pragma unroll
            for (int ni = 0; ni < 2; ni++) {
                int col = wcol + ni * 8 + 2 * tr;
                int r = row0 + mi * 16 + tq;
                if (r < NN) {
                    float2 v;
                    v.x = acc[mi][ni][0] + bias[ni][0];
                    v.y = acc[mi][ni][1] + bias[ni][1];
                    *(float2*)(g_xres + (size_t)r * DD + col) = v;
                }
                if (r + 8 < NN) {
                    float2 v;
                    v.x = acc[mi][ni][2] + bias[ni][0];
                    v.y = acc[mi][ni][3] + bias[ni][1];
                    *(float2*)(g_xres + (size_t)(r + 8) * DD + col) = v;
                }
            }
        }
    }
}

// ---------------------------------------------------------------------------
// Kernel 3: pocket pooling, atomic-free. Block = (graph b, slice s).
// ---------------------------------------------------------------------------
__global__ void pool_kernel(const float* __restrict__ mask) {
    __shared__ float sacc[8][KK * DD];
    __shared__ float scnt[8][KK];
    const int b = blockIdx.x / PS;
    const int s = blockIdx.x % PS;
    const int gs = g_gstart[b];
    const int len = g_gstart[b + 1] - gs;
    const int start = gs + (len * s) / PS;
    const int end = gs + (len * (s + 1)) / PS;

    const int wib = threadIdx.x >> 5;
    const int lane = threadIdx.x & 31;
    float* acc = sacc[wib];
    for (int i = lane; i < KK * DD; i += 32) acc[i] = 0.f;
    float cnt = 0.f;

    for (int n = start + wib; n < end; n += 8) {
        float m = (lane < KK) ? mask[(size_t)n * KK + lane] : 0.f;
        float4 xv = *(const float4*)(g_xres + (size_t)n * DD + lane * 4);
#pragma unroll
        for (int k = 0; k < KK; k++) {
            float mk = __shfl_sync(0xffffffffu, m, k);
            if (mk != 0.f) {
                float4* a = (float4*)(acc + k * DD + lane * 4);
                float4 v = *a;
                v.x += xv.x; v.y += xv.y; v.z += xv.z; v.w += xv.w;
                *a = v;
            }
        }
        cnt += m;
    }
    if (lane < KK) scnt[wib][lane] = cnt;
    __syncthreads();

    float* outp = g_part + (size_t)blockIdx.x * KK * DD;
    for (int i = threadIdx.x; i < KK * DD; i += blockDim.x) {
        float v = 0.f;
#pragma unroll
        for (int w = 0; w < 8; w++) v += sacc[w][i];
        outp[i] = v;
    }
    if (threadIdx.x < KK) {
        float c = 0.f;
#pragma unroll
        for (int w = 0; w < 8; w++) c += scnt[w][threadIdx.x];
        g_cntpart[blockIdx.x * KK + threadIdx.x] = c;
    }
}

// ---------------------------------------------------------------------------
// Kernel 3b: reduce partials -> g_psum, g_pcnt
// ---------------------------------------------------------------------------
__global__ void reduce_kernel() {
    int tid = blockIdx.x * blockDim.x + threadIdx.x;
    int stride = gridDim.x * blockDim.x;
    for (int i = tid; i < BB * KK * DD; i += stride) {
        int b = i / (KK * DD);
        int j = i % (KK * DD);
        float v = 0.f;
#pragma unroll
        for (int s = 0; s < PS; s++) v += g_part[(size_t)(b * PS + s) * KK * DD + j];
        g_psum[i] = v;
    }
    for (int i = tid; i < BB * KK; i += stride) {
        int b = i / KK;
        int k = i % KK;
        float c = 0.f;
#pragma unroll
        for (int s = 0; s < PS; s++) c += g_cntpart[(b * PS + s) * KK + k];
        g_pcnt[i] = c;
    }
}

// ---------------------------------------------------------------------------
// Kernel 4: pocket_emb = (psum/(cnt+1e-9)) @ Wv + bv. Warp per row (512 rows).
// ---------------------------------------------------------------------------
__global__ void pemb_kernel(const float* __restrict__ Wv, const float* __restrict__ bv) {
    const int lane = threadIdx.x & 31;
    const int r = blockIdx.x * (blockDim.x >> 5) + (threadIdx.x >> 5);
    if (r >= BB * KK) return;
    const float rinv = 1.f / (g_pcnt[r] + 1e-9f);
    const int c0 = lane * 4;
    float4 acc = *(const float4*)(bv + c0);
#pragma unroll 8
    for (int d = 0; d < DD; d++) {
        float a = g_psum[r * DD + d] * rinv;
        float4 w = __ldg((const float4*)(Wv + d * DD + c0));
        acc.x += a * w.x; acc.y += a * w.y; acc.z += a * w.z; acc.w += a * w.w;
    }
    *(float4*)(g_pemb + r * DD + c0) = acc;
}

// ---------------------------------------------------------------------------
// Kernel 5: residual pocket feedback + LayerNorm + ReLU. Warp per node.
// ---------------------------------------------------------------------------
__global__ void final_kernel(const float* __restrict__ mask, const int* __restrict__ batch,
                             const float* __restrict__ gamma, const float* __restrict__ beta,
                             float* __restrict__ out) {
    const int lane = threadIdx.x & 31;
    const int gw = blockIdx.x * (blockDim.x >> 5) + (threadIdx.x >> 5);
    const int tw = gridDim.x * (blockDim.x >> 5);
    const int c0 = lane * 4;
    const float4 gm = *(const float4*)(gamma + c0);
    const float4 bt = *(const float4*)(beta + c0);

    for (int n = gw; n < NN; n += tw) {
        int g = batch[n];
        float m = (lane < KK) ? mask[(size_t)n * KK + lane] : 0.f;
        float4 v = *(const float4*)(g_xres + (size_t)n * DD + c0);
        const float* pe = g_pemb + (size_t)g * KK * DD;
#pragma unroll
        for (int k = 0; k < KK; k++) {
            float mk = __shfl_sync(0xffffffffu, m, k);
            if (mk != 0.f) {
                float4 p = __ldg((const float4*)(pe + k * DD + c0));
                v.x += p.x; v.y += p.y; v.z += p.z; v.w += p.w;
            }
        }
        float s = v.x + v.y + v.z + v.w;
#pragma unroll
        for (int off = 16; off; off >>= 1) s += __shfl_xor_sync(0xffffffffu, s, off);
        float mu = s * (1.f / 128.f);
        float dx = v.x - mu, dy = v.y - mu, dz = v.z - mu, dw = v.w - mu;
        float sq = dx * dx + dy * dy + dz * dz + dw * dw;
#pragma unroll
        for (int off = 16; off; off >>= 1) sq += __shfl_xor_sync(0xffffffffu, sq, off);
        float rstd = rsqrtf(sq * (1.f / 128.f) + 1e-5f);
        float4 y;
        y.x = fmaxf(dx * rstd * gm.x + bt.x, 0.f);
        y.y = fmaxf(dy * rstd * gm.y + bt.y, 0.f);
        y.z = fmaxf(dz * rstd * gm.z + bt.z, 0.f);
        y.w = fmaxf(dw * rstd * gm.w + bt.w, 0.f);
        *(float4*)(out + (size_t)n * DD + c0) = y;
    }
}

// ---------------------------------------------------------------------------
extern "C" void kernel_launch(void* const* d_in, const int* in_sizes, int n_in,
                              void* d_out, int out_size) {
    const float* x     = (const float*)d_in[0];
    const int*   ei    = (const int*)d_in[1];
    const float* ea    = (const float*)d_in[2];
    const float* pmask = (const float*)d_in[3];
    const int*   batch = (const int*)d_in[4];
    const float* We    = (const float*)d_in[5];
    const float* be    = (const float*)d_in[6];
    const float* W1    = (const float*)d_in[7];
    const float* b1    = (const float*)d_in[8];
    const float* W2    = (const float*)d_in[9];
    const float* b2    = (const float*)d_in[10];
    const float* eps   = (const float*)d_in[11];
    const float* gamma = (const float*)d_in[12];
    const float* beta  = (const float*)d_in[13];
    const float* Wv    = (const float*)d_in[14];
    const float* bv    = (const float*)d_in[15];
    float* out = (float*)d_out;

    const int MLP_SMEM = 64 * PADW * 4;   // 33792 bytes (sA only)
    cudaFuncSetAttribute(mlp_fused_kernel, cudaFuncAttributeMaxDynamicSharedMemorySize, MLP_SMEM);

    init_kernel<<<2048, 256>>>(x, eps);
    bounds_kernel<<<(NN + 255) / 256, 256>>>(batch);
    wconv_kernel<<<64, 256>>>(W1, W2);
    edge_kernel<<<4096, 256>>>(x, ei, ea, We, be);
    mlp_fused_kernel<<<(NN + 63) / 64, 256, MLP_SMEM>>>(b1, b2);
    pool_kernel<<<BB * PS, 256>>>(pmask);
    reduce_kernel<<<64, 256>>>();
    pemb_kernel<<<(BB * KK + 7) / 8, 256>>>(Wv, bv);
    final_kernel<<<2048, 256>>>(pmask, batch, gamma, beta, out);
}